// round 6
// baseline (speedup 1.0000x reference)
#include <cuda_runtime.h>
#include <cstddef>

// Problem constants
#define BB    128
#define NN    1024
#define LL    512
#define DD    64
#define TPB   256                 // threads per block, 1 token row per thread
#define RB    64                  // regions per smem tile (16 KB per stage)
#define NTILE (NN / TPB)          // 4 token tiles
#define NTICKET (3 * BB * NTILE)  // 1536 work items
#define GRID  592                 // 148 SMs x 4 CTAs -> exactly one wave

// Scratch (no device allocations allowed -> __device__ globals)
__device__ float        g_part[NTICKET];  // partial sum(max) per (sim, b, tile)
__device__ float        g_ntokf[BB];
__device__ unsigned int g_ticket;         // zero-init; reset by last block
__device__ unsigned int g_done;           // zero-init; reset by last block

// Packed f32x2 ops (sm_100+)
#define FMA2(acc, a, b) asm("fma.rn.f32x2 %0, %1, %2, %0;" : "+l"(acc) : "l"(a), "l"(b))
#define ADD2(d, a, b)   asm("add.rn.f32x2 %0, %1, %2;"     : "=l"(d)  : "l"(a), "l"(b))

#define CP_ASYNC16(dst_s, src_g) \
    asm volatile("cp.async.cg.shared.global [%0], [%1], 16;" :: "r"(dst_s), "l"(src_g))
#define CP_COMMIT()  asm volatile("cp.async.commit_group;" ::: "memory")
#define CP_WAIT1()   asm volatile("cp.async.wait_group 1;" ::: "memory")

__device__ __forceinline__ float2 u64_as_f2(unsigned long long v) {
    float2 r;
    r.x = __uint_as_float((unsigned int)(v & 0xffffffffull));
    r.y = __uint_as_float((unsigned int)(v >> 32));
    return r;
}

// ---------------------------------------------------------------------------
__global__ __launch_bounds__(TPB) void fused_kernel(
    const float* __restrict__ text,
    const float* __restrict__ image,
    const float* __restrict__ tmask,
    const float* __restrict__ imask,
    const int* __restrict__ Iidx,
    const int* __restrict__ Sidx,
    float* __restrict__ out) {

    __shared__ float        sI[2][RB * DD];  // 2 x 16 KB region tiles
    __shared__ float        rsm[20];         // reduction scratch
    __shared__ unsigned int s_tkt;

    const int t = threadIdx.x;
    const int w = t >> 5, lane = t & 31;

    for (;;) {
        __syncthreads();                     // protect s_tkt / smem reuse
        if (t == 0) s_tkt = atomicAdd(&g_ticket, 1u);
        __syncthreads();
        const unsigned int tk = s_tkt;
        if (tk >= NTICKET) break;

        // decode: tk = (s*BB + b)*NTILE + tile
        const int tile = tk % NTILE;
        const int b    = (tk / NTILE) % BB;
        const int s    = tk / (BB * NTILE);
        const int tb   = (s == 1) ? Sidx[b] : b;   // text batch index
        const int ib   = (s == 2) ? Iidx[b] : b;   // image batch index

        // --- per-ticket valid counts from prefix masks (coalesced sums) ---
        float sa = 0.f, sb = 0.f;
        #pragma unroll
        for (int i = 0; i < NN / TPB; i++) sa += tmask[tb * NN + i * TPB + t];
        #pragma unroll
        for (int i = 0; i < LL / TPB; i++) sb += imask[ib * LL + i * TPB + t];
        #pragma unroll
        for (int o = 16; o > 0; o >>= 1) {
            sa += __shfl_down_sync(0xffffffffu, sa, o);
            sb += __shfl_down_sync(0xffffffffu, sb, o);
        }
        if (lane == 0) { rsm[2 * w] = sa; rsm[2 * w + 1] = sb; }
        __syncthreads();
        if (w == 0) {
            float x = (lane < 8) ? rsm[2 * lane] : 0.f;
            float y = (lane < 8) ? rsm[2 * lane + 1] : 0.f;
            #pragma unroll
            for (int o = 4; o > 0; o >>= 1) {
                x += __shfl_down_sync(0xffffffffu, x, o);
                y += __shfl_down_sync(0xffffffffu, y, o);
            }
            if (lane == 0) { rsm[16] = x; rsm[17] = y; }
        }
        __syncthreads();
        const float ntok_f = rsm[16];
        const int ntok = (int)(ntok_f + 0.5f);
        const int nreg = (int)(rsm[17] + 0.5f);

        if (s == 0 && tile == 0 && t == 0) g_ntokf[b] = ntok_f;  // tb==b here

        if (tile * TPB >= ntok) {            // whole tile past valid prefix
            if (t == 0) g_part[tk] = 0.f;
            continue;
        }

        const float4* isrc =
            reinterpret_cast<const float4*>(image + (size_t)ib * LL * DD);
        const int nchunk = (nreg + RB - 1) / RB;

        // Prefetch chunk 0 into stage 0 (full RB rows safe: LL % RB == 0)
        {
            #pragma unroll
            for (int i = 0; i < (RB * DD / 4) / TPB; i++) {
                int idx = i * TPB + t;
                unsigned int ds = (unsigned int)__cvta_generic_to_shared(
                    reinterpret_cast<float4*>(sI[0]) + idx);
                CP_ASYNC16(ds, isrc + idx);
            }
            CP_COMMIT();
        }

        const int n = tile * TPB + t;
        const bool tv = (n < ntok);

        // Token row resident in registers as 32 packed f32x2 values
        unsigned long long tr[DD / 2];
        if (tv) {
            const ulonglong2* trow =
                reinterpret_cast<const ulonglong2*>(text + ((size_t)tb * NN + n) * DD);
            #pragma unroll
            for (int i = 0; i < DD / 4; i++) {
                ulonglong2 v = trow[i];
                tr[2 * i] = v.x; tr[2 * i + 1] = v.y;
            }
        }

        float mx = __int_as_float(0xff800000);   // -inf

        for (int c = 0; c < nchunk; c++) {
            if (c + 1 < nchunk) {                // prefetch next stage
                const float4* src = isrc + (c + 1) * RB * (DD / 4);
                float4* dstp = reinterpret_cast<float4*>(sI[(c + 1) & 1]);
                #pragma unroll
                for (int i = 0; i < (RB * DD / 4) / TPB; i++) {
                    int idx = i * TPB + t;
                    unsigned int ds = (unsigned int)__cvta_generic_to_shared(dstp + idx);
                    CP_ASYNC16(ds, src + idx);
                }
            }
            CP_COMMIT();
            CP_WAIT1();                          // chunk c complete
            __syncthreads();

            const int lcount = min(RB, nreg - c * RB);
            const float* stage = sI[c & 1];

            if (tv) {
                for (int l = 0; l < lcount; l++) {
                    // all threads read the same region row -> smem broadcast
                    const ulonglong2* sv =
                        reinterpret_cast<const ulonglong2*>(stage + l * DD);
                    unsigned long long c0 = 0ull, c1 = 0ull, c2 = 0ull, c3 = 0ull;
                    #pragma unroll
                    for (int j = 0; j < DD / 8; j++) {   // 2x LDS.128 + 4x FFMA2
                        ulonglong2 v0 = sv[2 * j], v1 = sv[2 * j + 1];
                        FMA2(c0, tr[4 * j],     v0.x);
                        FMA2(c1, tr[4 * j + 1], v0.y);
                        FMA2(c2, tr[4 * j + 2], v1.x);
                        FMA2(c3, tr[4 * j + 3], v1.y);
                    }
                    unsigned long long s01, s23, sall;
                    ADD2(s01, c0, c1);
                    ADD2(s23, c2, c3);
                    ADD2(sall, s01, s23);
                    float2 f = u64_as_f2(sall);
                    mx = fmaxf(mx, f.x + f.y);
                }
            }
            __syncthreads();                     // stage free before reuse
        }

        // sum of per-token maxes over this tile (prefix mask -> weight 1)
        float v = tv ? mx : 0.f;
        #pragma unroll
        for (int o = 16; o > 0; o >>= 1) v += __shfl_down_sync(0xffffffffu, v, o);
        if (lane == 0) rsm[w] = v;
        __syncthreads();
        if (w == 0) {
            float x = (lane < 8) ? rsm[lane] : 0.f;
            #pragma unroll
            for (int o = 4; o > 0; o >>= 1) x += __shfl_down_sync(0xffffffffu, x, o);
            if (lane == 0) g_part[tk] = x;
        }
        // loop-top __syncthreads() protects rsm
    }

    // ---- completion: last block computes the loss and resets counters ----
    __threadfence();
    __shared__ unsigned int s_prev;
    if (t == 0) s_prev = atomicAdd(&g_done, 1u);
    __syncthreads();
    if (s_prev != GRID - 1) return;
    __threadfence();

    float per = 0.f;
    if (t < BB) {
        const int b = t;
        float anchor = 0.f, simp = 0.f, iimp = 0.f;
        #pragma unroll
        for (int tile = 0; tile < NTILE; tile++) {
            anchor += g_part[(0 * BB + b) * NTILE + tile];
            simp   += g_part[(1 * BB + b) * NTILE + tile];
            iimp   += g_part[(2 * BB + b) * NTILE + tile];
        }
        const float nb = g_ntokf[b];
        anchor /= nb;
        iimp   /= nb;
        simp   /= g_ntokf[Sidx[b]];
        per = fmaxf(1.f + iimp - anchor, 0.f) + fmaxf(1.f + simp - anchor, 0.f);
    }
    #pragma unroll
    for (int o = 16; o > 0; o >>= 1) per += __shfl_down_sync(0xffffffffu, per, o);
    if (lane == 0) rsm[w] = per;
    __syncthreads();
    if (t == 0) {
        float tot = rsm[0] + rsm[1] + rsm[2] + rsm[3];  // only warps 0-3 hold b<128
        out[0] = tot / (float)BB;
        g_ticket = 0u;                                  // reset for next replay
        g_done   = 0u;
    }
}

// ---------------------------------------------------------------------------
extern "C" void kernel_launch(void* const* d_in, const int* in_sizes, int n_in,
                              void* d_out, int out_size) {
    const float* text  = (const float*)d_in[0];   // (B, N, D) f32
    const float* image = (const float*)d_in[1];   // (B, L, D) f32
    const float* tmask = (const float*)d_in[2];   // (B, N) f32
    const float* imask = (const float*)d_in[3];   // (B, L) f32
    const int*   Iidx  = (const int*)d_in[4];     // (B,) i32
    const int*   Sidx  = (const int*)d_in[5];     // (B,) i32
    (void)in_sizes; (void)n_in; (void)out_size;

    fused_kernel<<<GRID, TPB>>>(text, image, tmask, imask, Iidx, Sidx,
                                (float*)d_out);
}

// round 7
// speedup vs baseline: 1.1755x; 1.1755x over previous
#include <cuda_runtime.h>
#include <cstddef>

// Problem constants
#define BB    128
#define NN    1024
#define LL    512
#define DD    64
#define TPB   128                 // threads per block; each thread owns 2 token rows
#define TOKT  256                 // tokens per tile (TPB * 2)
#define RB    64                  // regions per smem tile (16 KB per stage)
#define NTILE (NN / TOKT)         // 4 token tiles
#define NTICKET (3 * BB * NTILE)  // 1536 work items
#define GRID  296                 // 148 SMs x 2 CTAs -> one wave at ~175 regs

// Scratch (no device allocations allowed -> __device__ globals)
__device__ float        g_part[NTICKET];  // partial sum(max) per (sim, b, tile)
__device__ float        g_ntokf[BB];
__device__ unsigned int g_ticket;         // zero-init; reset by last block
__device__ unsigned int g_done;           // zero-init; reset by last block

// Packed f32x2 ops (sm_100+)
#define FMA2(acc, a, b) asm("fma.rn.f32x2 %0, %1, %2, %0;" : "+l"(acc) : "l"(a), "l"(b))
#define ADD2(d, a, b)   asm("add.rn.f32x2 %0, %1, %2;"     : "=l"(d)  : "l"(a), "l"(b))

#define CP_ASYNC16(dst_s, src_g) \
    asm volatile("cp.async.cg.shared.global [%0], [%1], 16;" :: "r"(dst_s), "l"(src_g))
#define CP_COMMIT()  asm volatile("cp.async.commit_group;" ::: "memory")
#define CP_WAIT1()   asm volatile("cp.async.wait_group 1;" ::: "memory")

__device__ __forceinline__ float2 u64_as_f2(unsigned long long v) {
    float2 r;
    r.x = __uint_as_float((unsigned int)(v & 0xffffffffull));
    r.y = __uint_as_float((unsigned int)(v >> 32));
    return r;
}

// ---------------------------------------------------------------------------
__global__ __launch_bounds__(TPB, 2) void fused_kernel(
    const float* __restrict__ text,
    const float* __restrict__ image,
    const float* __restrict__ tmask,
    const float* __restrict__ imask,
    const int* __restrict__ Iidx,
    const int* __restrict__ Sidx,
    float* __restrict__ out) {

    __shared__ float        sI[2][RB * DD];  // 2 x 16 KB region tiles
    __shared__ float        rsm[12];         // reduction scratch (4 warps)
    __shared__ unsigned int s_tkt;

    const int t = threadIdx.x;
    const int w = t >> 5, lane = t & 31;

    for (;;) {
        __syncthreads();                     // protect s_tkt / smem reuse
        if (t == 0) s_tkt = atomicAdd(&g_ticket, 1u);
        __syncthreads();
        const unsigned int tk = s_tkt;
        if (tk >= NTICKET) break;

        // decode: tk = (s*BB + b)*NTILE + tile
        const int tile = tk % NTILE;
        const int b    = (tk / NTILE) % BB;
        const int s    = tk / (BB * NTILE);
        const int tb   = (s == 1) ? Sidx[b] : b;   // text batch index
        const int ib   = (s == 2) ? Iidx[b] : b;   // image batch index

        // --- per-ticket valid counts from prefix masks (coalesced sums) ---
        float sa = 0.f, sb = 0.f;
        #pragma unroll
        for (int i = 0; i < NN / TPB; i++) sa += tmask[tb * NN + i * TPB + t];
        #pragma unroll
        for (int i = 0; i < LL / TPB; i++) sb += imask[ib * LL + i * TPB + t];
        #pragma unroll
        for (int o = 16; o > 0; o >>= 1) {
            sa += __shfl_down_sync(0xffffffffu, sa, o);
            sb += __shfl_down_sync(0xffffffffu, sb, o);
        }
        if (lane == 0) { rsm[2 * w] = sa; rsm[2 * w + 1] = sb; }
        __syncthreads();
        if (t == 0) {
            rsm[8] = rsm[0] + rsm[2] + rsm[4] + rsm[6];
            rsm[9] = rsm[1] + rsm[3] + rsm[5] + rsm[7];
        }
        __syncthreads();
        const float ntok_f = rsm[8];
        const int ntok = (int)(ntok_f + 0.5f);
        const int nreg = (int)(rsm[9] + 0.5f);

        if (s == 0 && tile == 0 && t == 0) g_ntokf[b] = ntok_f;  // tb==b here

        if (tile * TOKT >= ntok) {           // whole tile past valid prefix
            if (t == 0) g_part[tk] = 0.f;
            continue;
        }

        const float4* isrc =
            reinterpret_cast<const float4*>(image + (size_t)ib * LL * DD);
        const int nchunk = (nreg + RB - 1) / RB;

        // Prefetch chunk 0 into stage 0 (full RB rows safe: LL % RB == 0)
        {
            #pragma unroll
            for (int i = 0; i < (RB * DD / 4) / TPB; i++) {
                int idx = i * TPB + t;
                unsigned int ds = (unsigned int)__cvta_generic_to_shared(
                    reinterpret_cast<float4*>(sI[0]) + idx);
                CP_ASYNC16(ds, isrc + idx);
            }
            CP_COMMIT();
        }

        const int n0 = tile * TOKT + t;          // token 0
        const int n1 = n0 + TPB;                 // token 1
        const bool tv0 = (n0 < ntok);
        const bool tv1 = (n1 < ntok);

        // Two token rows resident in registers (2 x 32 packed f32x2)
        unsigned long long tr0[DD / 2], tr1[DD / 2];
        if (tv0) {
            const ulonglong2* p =
                reinterpret_cast<const ulonglong2*>(text + ((size_t)tb * NN + n0) * DD);
            #pragma unroll
            for (int i = 0; i < DD / 4; i++) {
                ulonglong2 v = p[i];
                tr0[2 * i] = v.x; tr0[2 * i + 1] = v.y;
            }
        }
        if (tv1) {
            const ulonglong2* p =
                reinterpret_cast<const ulonglong2*>(text + ((size_t)tb * NN + n1) * DD);
            #pragma unroll
            for (int i = 0; i < DD / 4; i++) {
                ulonglong2 v = p[i];
                tr1[2 * i] = v.x; tr1[2 * i + 1] = v.y;
            }
        }

        float mx0 = __int_as_float(0xff800000);  // -inf
        float mx1 = __int_as_float(0xff800000);

        for (int c = 0; c < nchunk; c++) {
            if (c + 1 < nchunk) {                // prefetch next stage
                const float4* src = isrc + (c + 1) * RB * (DD / 4);
                float4* dstp = reinterpret_cast<float4*>(sI[(c + 1) & 1]);
                #pragma unroll
                for (int i = 0; i < (RB * DD / 4) / TPB; i++) {
                    int idx = i * TPB + t;
                    unsigned int ds = (unsigned int)__cvta_generic_to_shared(dstp + idx);
                    CP_ASYNC16(ds, src + idx);
                }
            }
            CP_COMMIT();
            CP_WAIT1();                          // chunk c complete
            __syncthreads();

            const int lcount = min(RB, nreg - c * RB);
            const float* stage = sI[c & 1];

            if (tv0) {
                for (int l = 0; l < lcount; l++) {
                    // all threads read the same region row -> smem broadcast;
                    // each LDS feeds BOTH token rows (2x FMA per byte loaded)
                    const ulonglong2* sv =
                        reinterpret_cast<const ulonglong2*>(stage + l * DD);
                    unsigned long long a0 = 0ull, a1 = 0ull, a2 = 0ull, a3 = 0ull;
                    unsigned long long b0 = 0ull, b1 = 0ull, b2 = 0ull, b3 = 0ull;
                    #pragma unroll
                    for (int j = 0; j < DD / 8; j++) {   // 2x LDS.128 + 8x FFMA2
                        ulonglong2 v0 = sv[2 * j], v1 = sv[2 * j + 1];
                        FMA2(a0, tr0[4 * j],     v0.x);
                        FMA2(b0, tr1[4 * j],     v0.x);
                        FMA2(a1, tr0[4 * j + 1], v0.y);
                        FMA2(b1, tr1[4 * j + 1], v0.y);
                        FMA2(a2, tr0[4 * j + 2], v1.x);
                        FMA2(b2, tr1[4 * j + 2], v1.x);
                        FMA2(a3, tr0[4 * j + 3], v1.y);
                        FMA2(b3, tr1[4 * j + 3], v1.y);
                    }
                    unsigned long long sA, sB, sC, sD;
                    ADD2(sA, a0, a1); ADD2(sB, a2, a3); ADD2(sA, sA, sB);
                    ADD2(sC, b0, b1); ADD2(sD, b2, b3); ADD2(sC, sC, sD);
                    float2 fa = u64_as_f2(sA);
                    float2 fb = u64_as_f2(sC);
                    mx0 = fmaxf(mx0, fa.x + fa.y);
                    mx1 = fmaxf(mx1, fb.x + fb.y);
                }
            }
            __syncthreads();                     // stage free before reuse
        }

        // sum of per-token maxes over this tile (prefix mask -> weight 1)
        float v = (tv0 ? mx0 : 0.f) + (tv1 ? mx1 : 0.f);
        #pragma unroll
        for (int o = 16; o > 0; o >>= 1) v += __shfl_down_sync(0xffffffffu, v, o);
        if (lane == 0) rsm[w] = v;
        __syncthreads();
        if (t == 0) g_part[tk] = rsm[0] + rsm[1] + rsm[2] + rsm[3];
        // loop-top __syncthreads() protects rsm
    }

    // ---- completion: last block computes the loss and resets counters ----
    __threadfence();
    __shared__ unsigned int s_prev;
    if (t == 0) s_prev = atomicAdd(&g_done, 1u);
    __syncthreads();
    if (s_prev != GRID - 1) return;
    __threadfence();

    // 128 threads == BB: one batch element per thread
    const int b = t;
    float anchor = 0.f, simp = 0.f, iimp = 0.f;
    #pragma unroll
    for (int tile = 0; tile < NTILE; tile++) {
        anchor += g_part[(0 * BB + b) * NTILE + tile];
        simp   += g_part[(1 * BB + b) * NTILE + tile];
        iimp   += g_part[(2 * BB + b) * NTILE + tile];
    }
    const float nb = g_ntokf[b];
    anchor /= nb;
    iimp   /= nb;
    simp   /= g_ntokf[Sidx[b]];
    float per = fmaxf(1.f + iimp - anchor, 0.f) + fmaxf(1.f + simp - anchor, 0.f);

    #pragma unroll
    for (int o = 16; o > 0; o >>= 1) per += __shfl_down_sync(0xffffffffu, per, o);
    if (lane == 0) rsm[w] = per;
    __syncthreads();
    if (t == 0) {
        out[0] = (rsm[0] + rsm[1] + rsm[2] + rsm[3]) / (float)BB;
        g_ticket = 0u;                           // reset for next replay
        g_done   = 0u;
    }
}

// ---------------------------------------------------------------------------
extern "C" void kernel_launch(void* const* d_in, const int* in_sizes, int n_in,
                              void* d_out, int out_size) {
    const float* text  = (const float*)d_in[0];   // (B, N, D) f32
    const float* image = (const float*)d_in[1];   // (B, L, D) f32
    const float* tmask = (const float*)d_in[2];   // (B, N) f32
    const float* imask = (const float*)d_in[3];   // (B, L) f32
    const int*   Iidx  = (const int*)d_in[4];     // (B,) i32
    const int*   Sidx  = (const int*)d_in[5];     // (B,) i32
    (void)in_sizes; (void)n_in; (void)out_size;

    fused_kernel<<<GRID, TPB>>>(text, image, tmask, imask, Iidx, Sidx,
                                (float*)d_out);
}

// round 10
// speedup vs baseline: 1.1983x; 1.0194x over previous
#include <cuda_runtime.h>
#include <cstddef>

// Problem constants
#define BB    128
#define NN    1024
#define LL    512
#define DD    64
#define TPB   128                 // threads per block; each thread owns 2 token rows
#define TOKT  256                 // tokens per tile (TPB * 2)
#define RB    64                  // regions per smem tile (16 KB per stage)
#define NTILE (NN / TOKT)         // 4 token tiles
#define NTICKET (3 * BB * NTILE)  // 1536 work items
#define GRID  296                 // 148 SMs x 2 CTAs -> one wave

// Scratch (no device allocations allowed -> __device__ globals)
__device__ float        g_part[NTICKET];  // partial sum(max) per (sim, b, tile)
__device__ float        g_ntokf[BB];
__device__ unsigned int g_ticket;         // zero-init; reset by last block
__device__ unsigned int g_done;           // zero-init; reset by last block

// Packed f32x2 ops (sm_100+)
#define FMA2(acc, a, b) asm("fma.rn.f32x2 %0, %1, %2, %0;" : "+l"(acc) : "l"(a), "l"(b))
#define ADD2(d, a, b)   asm("add.rn.f32x2 %0, %1, %2;"     : "=l"(d)  : "l"(a), "l"(b))

#define CP_ASYNC16(dst_s, src_g) \
    asm volatile("cp.async.cg.shared.global [%0], [%1], 16;" :: "r"(dst_s), "l"(src_g))
#define CP_COMMIT()  asm volatile("cp.async.commit_group;" ::: "memory")
#define CP_WAIT1()   asm volatile("cp.async.wait_group 1;" ::: "memory")

__device__ __forceinline__ float2 u64_as_f2(unsigned long long v) {
    float2 r;
    r.x = __uint_as_float((unsigned int)(v & 0xffffffffull));
    r.y = __uint_as_float((unsigned int)(v >> 32));
    return r;
}

// Load one half-row (32 floats = 8 x LDS.128) into registers
#define LOADHALF(dst, base_ptr)                                        \
    do {                                                               \
        const ulonglong2* _p = (const ulonglong2*)(base_ptr);          \
        _Pragma("unroll")                                              \
        for (int _j = 0; _j < 8; _j++) (dst)[_j] = _p[_j];             \
    } while (0)

// 32 FFMA2: half-row h of the region row against both token rows
#define COMPUTEHALF(buf, h)                                            \
    do {                                                               \
        _Pragma("unroll")                                              \
        for (int _j = 0; _j < 8; _j++) {                               \
            ulonglong2 _v = (buf)[_j];                                 \
            FMA2(a0, tr0[(h) * 16 + 2 * _j],     _v.x);                \
            FMA2(b0, tr1[(h) * 16 + 2 * _j],     _v.x);                \
            FMA2(a1, tr0[(h) * 16 + 2 * _j + 1], _v.y);                \
            FMA2(b1, tr1[(h) * 16 + 2 * _j + 1], _v.y);                \
        }                                                              \
    } while (0)

// ---------------------------------------------------------------------------
__global__ __launch_bounds__(TPB, 2) void fused_kernel(
    const float* __restrict__ text,
    const float* __restrict__ image,
    const float* __restrict__ tmask,
    const float* __restrict__ imask,
    const int* __restrict__ Iidx,
    const int* __restrict__ Sidx,
    float* __restrict__ out) {

    __shared__ float        sI[2][RB * DD];  // 2 x 16 KB region tiles
    __shared__ float        rsm[12];         // reduction scratch (4 warps)
    __shared__ unsigned int s_tkt;

    const int t = threadIdx.x;
    const int w = t >> 5, lane = t & 31;

    for (;;) {
        __syncthreads();                     // protect s_tkt / smem reuse
        if (t == 0) s_tkt = atomicAdd(&g_ticket, 1u);
        __syncthreads();
        const unsigned int tk = s_tkt;
        if (tk >= NTICKET) break;

        // decode: tk = (s*BB + b)*NTILE + tile
        const int tile = tk % NTILE;
        const int b    = (tk / NTILE) % BB;
        const int s    = tk / (BB * NTILE);
        const int tb   = (s == 1) ? Sidx[b] : b;   // text batch index
        const int ib   = (s == 2) ? Iidx[b] : b;   // image batch index

        // --- per-ticket valid counts from prefix masks (coalesced sums) ---
        float sa = 0.f, sb = 0.f;
        #pragma unroll
        for (int i = 0; i < NN / TPB; i++) sa += tmask[tb * NN + i * TPB + t];
        #pragma unroll
        for (int i = 0; i < LL / TPB; i++) sb += imask[ib * LL + i * TPB + t];
        #pragma unroll
        for (int o = 16; o > 0; o >>= 1) {
            sa += __shfl_down_sync(0xffffffffu, sa, o);
            sb += __shfl_down_sync(0xffffffffu, sb, o);
        }
        if (lane == 0) { rsm[2 * w] = sa; rsm[2 * w + 1] = sb; }
        __syncthreads();
        if (t == 0) {
            rsm[8] = rsm[0] + rsm[2] + rsm[4] + rsm[6];
            rsm[9] = rsm[1] + rsm[3] + rsm[5] + rsm[7];
        }
        __syncthreads();
        const float ntok_f = rsm[8];
        const int ntok = (int)(ntok_f + 0.5f);
        const int nreg = (int)(rsm[9] + 0.5f);

        if (s == 0 && tile == 0 && t == 0) g_ntokf[b] = ntok_f;  // tb==b here

        if (tile * TOKT >= ntok) {           // whole tile past valid prefix
            if (t == 0) g_part[tk] = 0.f;
            continue;
        }

        const float4* isrc =
            reinterpret_cast<const float4*>(image + (size_t)ib * LL * DD);
        const int nchunk = (nreg + RB - 1) / RB;

        // Prefetch chunk 0 into stage 0 (full RB rows safe: LL % RB == 0)
        {
            #pragma unroll
            for (int i = 0; i < (RB * DD / 4) / TPB; i++) {
                int idx = i * TPB + t;
                unsigned int ds = (unsigned int)__cvta_generic_to_shared(
                    reinterpret_cast<float4*>(sI[0]) + idx);
                CP_ASYNC16(ds, isrc + idx);
            }
            CP_COMMIT();
        }

        const int n0 = tile * TOKT + t;          // token 0
        const int n1 = n0 + TPB;                 // token 1
        const bool tv0 = (n0 < ntok);
        const bool tv1 = (n1 < ntok);

        // Two token rows resident in registers (2 x 32 packed f32x2)
        unsigned long long tr0[DD / 2], tr1[DD / 2];
        if (tv0) {
            const ulonglong2* p =
                reinterpret_cast<const ulonglong2*>(text + ((size_t)tb * NN + n0) * DD);
            #pragma unroll
            for (int i = 0; i < DD / 4; i++) {
                ulonglong2 v = p[i];
                tr0[2 * i] = v.x; tr0[2 * i + 1] = v.y;
            }
        }
        if (tv1) {
            const ulonglong2* p =
                reinterpret_cast<const ulonglong2*>(text + ((size_t)tb * NN + n1) * DD);
            #pragma unroll
            for (int i = 0; i < DD / 4; i++) {
                ulonglong2 v = p[i];
                tr1[2 * i] = v.x; tr1[2 * i + 1] = v.y;
            }
        }

        float mx0 = __int_as_float(0xff800000);  // -inf
        float mx1 = __int_as_float(0xff800000);

        for (int c = 0; c < nchunk; c++) {
            if (c + 1 < nchunk) {                // prefetch next stage
                const float4* src = isrc + (c + 1) * RB * (DD / 4);
                float4* dstp = reinterpret_cast<float4*>(sI[(c + 1) & 1]);
                #pragma unroll
                for (int i = 0; i < (RB * DD / 4) / TPB; i++) {
                    int idx = i * TPB + t;
                    unsigned int ds = (unsigned int)__cvta_generic_to_shared(dstp + idx);
                    CP_ASYNC16(ds, src + idx);
                }
            }
            CP_COMMIT();
            CP_WAIT1();                          // chunk c complete
            __syncthreads();

            const int lcount = min(RB, nreg - c * RB);
            const float* stage = sI[c & 1];

            if (tv0) {
                // Software-pipelined region loop: half-row register double
                // buffer hides LDS latency behind 32-FFMA2 compute blocks.
                ulonglong2 bufA[8], bufB[8];
                LOADHALF(bufA, stage);                       // row 0, half 0
                for (int l = 0; l < lcount; l++) {
                    unsigned long long a0 = 0ull, a1 = 0ull;
                    unsigned long long b0 = 0ull, b1 = 0ull;
                    const float* row = stage + l * DD;
                    LOADHALF(bufB, row + 32);                // row l, half 1
                    COMPUTEHALF(bufA, 0);                    // row l, half 0
                    // Prefetch row l+1 half 0. (l+1)&(RB-1) is always a valid
                    // fully-written stage row (cp.async fills all RB rows);
                    // the wrapped value on the final iteration is discarded.
                    const int lp = (l + 1) & (RB - 1);
                    LOADHALF(bufA, stage + lp * DD);
                    COMPUTEHALF(bufB, 1);                    // row l, half 1

                    unsigned long long sA, sB;
                    ADD2(sA, a0, a1);
                    ADD2(sB, b0, b1);
                    float2 fa = u64_as_f2(sA);
                    float2 fb = u64_as_f2(sB);
                    mx0 = fmaxf(mx0, fa.x + fa.y);
                    mx1 = fmaxf(mx1, fb.x + fb.y);
                }
            }
            __syncthreads();                     // stage free before reuse
        }

        // sum of per-token maxes over this tile (prefix mask -> weight 1)
        float v = (tv0 ? mx0 : 0.f) + (tv1 ? mx1 : 0.f);
        #pragma unroll
        for (int o = 16; o > 0; o >>= 1) v += __shfl_down_sync(0xffffffffu, v, o);
        if (lane == 0) rsm[w] = v;
        __syncthreads();
        if (t == 0) g_part[tk] = rsm[0] + rsm[1] + rsm[2] + rsm[3];
        // loop-top __syncthreads() protects rsm
    }

    // ---- completion: last block computes the loss and resets counters ----
    __threadfence();
    __shared__ unsigned int s_prev;
    if (t == 0) s_prev = atomicAdd(&g_done, 1u);
    __syncthreads();
    if (s_prev != GRID - 1) return;
    __threadfence();

    // 128 threads == BB: one batch element per thread
    const int b = t;
    float anchor = 0.f, simp = 0.f, iimp = 0.f;
    #pragma unroll
    for (int tile = 0; tile < NTILE; tile++) {
        anchor += g_part[(0 * BB + b) * NTILE + tile];
        simp   += g_part[(1 * BB + b) * NTILE + tile];
        iimp   += g_part[(2 * BB + b) * NTILE + tile];
    }
    const float nb = g_ntokf[b];
    anchor /= nb;
    iimp   /= nb;
    simp   /= g_ntokf[Sidx[b]];
    float per = fmaxf(1.f + iimp - anchor, 0.f) + fmaxf(1.f + simp - anchor, 0.f);

    #pragma unroll
    for (int o = 16; o > 0; o >>= 1) per += __shfl_down_sync(0xffffffffu, per, o);
    if (lane == 0) rsm[w] = per;
    __syncthreads();
    if (t == 0) {
        out[0] = (rsm[0] + rsm[1] + rsm[2] + rsm[3]) / (float)BB;
        g_ticket = 0u;                           // reset for next replay
        g_done   = 0u;
    }
}

// ---------------------------------------------------------------------------
extern "C" void kernel_launch(void* const* d_in, const int* in_sizes, int n_in,
                              void* d_out, int out_size) {
    const float* text  = (const float*)d_in[0];   // (B, N, D) f32
    const float* image = (const float*)d_in[1];   // (B, L, D) f32
    const float* tmask = (const float*)d_in[2];   // (B, N) f32
    const float* imask = (const float*)d_in[3];   // (B, L) f32
    const int*   Iidx  = (const int*)d_in[4];     // (B,) i32
    const int*   Sidx  = (const int*)d_in[5];     // (B,) i32
    (void)in_sizes; (void)n_in; (void)out_size;

    fused_kernel<<<GRID, TPB>>>(text, image, tmask, imask, Iidx, Sidx,
                                (float*)d_out);
}

// round 12
// speedup vs baseline: 1.8635x; 1.5550x over previous
#include <cuda_runtime.h>
#include <cuda_bf16.h>
#include <cstdint>
#include <cstddef>

// Problem constants
#define BB 128
#define NN 1024
#define LL 512
#define DD 64
#define MT 128                    // tokens per M tile
#define NMT (NN / MT)             // 8 M tiles
#define NTICKET (3 * BB * NMT)    // 3072 work items
#define TPB 128                   // 4 warps; warp owns 32 token rows
#define GRID 296                  // 148 SMs x 2 CTAs
#define RB 64                     // regions per B chunk
#define STRIDE 144                // padded smem row stride bytes (72 bf16) -> LDSM conflict-free

// Scratch (no device allocations allowed -> __device__ globals)
__device__ __align__(16) __nv_bfloat16 g_thi[BB * NN * DD];
__device__ __align__(16) __nv_bfloat16 g_tlo[BB * NN * DD];
__device__ __align__(16) __nv_bfloat16 g_ihi[BB * LL * DD];
__device__ __align__(16) __nv_bfloat16 g_ilo[BB * LL * DD];
__device__ float         g_part[NTICKET];
__device__ float         g_ntokf[BB];
__device__ unsigned int  g_ticket;   // zero-init; reset by last block
__device__ unsigned int  g_done;

// ---------------------------------------------------------------------------
// PTX helpers (all supported on base sm_103 target: sm_80+ features only)
// ---------------------------------------------------------------------------
__device__ __forceinline__ uint32_t smem_to_u32(const void* p) {
    uint32_t a;
    asm("{ .reg .u64 t; cvta.to.shared.u64 t, %1; cvt.u32.u64 %0, t; }"
        : "=r"(a) : "l"(p));
    return a;
}

#define LDSM4(r, addr) \
    asm volatile("ldmatrix.sync.aligned.m8n8.x4.shared.b16 {%0,%1,%2,%3}, [%4];" \
        : "=r"((r)[0]), "=r"((r)[1]), "=r"((r)[2]), "=r"((r)[3]) : "r"(addr))
#define LDSM2(r, addr) \
    asm volatile("ldmatrix.sync.aligned.m8n8.x2.shared.b16 {%0,%1}, [%2];" \
        : "=r"((r)[0]), "=r"((r)[1]) : "r"(addr))

#define MMA16816(d, a, b) \
    asm volatile("mma.sync.aligned.m16n8k16.row.col.f32.bf16.bf16.f32 " \
        "{%0,%1,%2,%3}, {%4,%5,%6,%7}, {%8,%9}, {%0,%1,%2,%3};" \
        : "+f"((d)[0]), "+f"((d)[1]), "+f"((d)[2]), "+f"((d)[3]) \
        : "r"((a)[0]), "r"((a)[1]), "r"((a)[2]), "r"((a)[3]), \
          "r"((b)[0]), "r"((b)[1]))

#define CP_ASYNC16(dst_s, src_g) \
    asm volatile("cp.async.cg.shared.global [%0], [%1], 16;" :: "r"(dst_s), "l"(src_g))
#define CP_COMMIT() asm volatile("cp.async.commit_group;" ::: "memory")
#define CP_WAIT1()  asm volatile("cp.async.wait_group 1;" ::: "memory")

// ldmatrix x4 address for A tile at (row0, k-byte kb): 16x16 tile, 4 8x8 mats
__device__ __forceinline__ uint32_t a_addr(uint32_t base, int row0, int kb, int lane) {
    int r = row0 + (lane & 7) + ((lane >> 3) & 1) * 8;
    return base + r * STRIDE + kb + ((lane >> 4) & 1) * 16;
}
// ldmatrix x2 address for B tile at (nrow0, kb): 8 n-rows x 16 k
__device__ __forceinline__ uint32_t b_addr(uint32_t base, int nrow0, int kb, int lane) {
    int l = lane & 15;
    return base + (nrow0 + (l & 7)) * STRIDE + kb + ((l >> 3) & 1) * 16;
}

// ---------------------------------------------------------------------------
// convert: fp32 -> (hi, lo) bf16 split, same (b, row, d) layout
// ---------------------------------------------------------------------------
__global__ void convert_kernel(const float* __restrict__ text,
                               const float* __restrict__ image) {
    const int NT4 = (BB * NN * DD) / 4;
    const int NI4 = (BB * LL * DD) / 4;
    int idx = blockIdx.x * blockDim.x + threadIdx.x;
    int stride = gridDim.x * blockDim.x;
    for (int i = idx; i < NT4 + NI4; i += stride) {
        const float4* src; __nv_bfloat16 *hi, *lo; int j;
        if (i < NT4) { src = (const float4*)text;  hi = g_thi; lo = g_tlo; j = i; }
        else         { src = (const float4*)image; hi = g_ihi; lo = g_ilo; j = i - NT4; }
        float4 v = src[j];
        __nv_bfloat16 h[4], l[4];
        h[0] = __float2bfloat16_rn(v.x); l[0] = __float2bfloat16_rn(v.x - __bfloat162float(h[0]));
        h[1] = __float2bfloat16_rn(v.y); l[1] = __float2bfloat16_rn(v.y - __bfloat162float(h[1]));
        h[2] = __float2bfloat16_rn(v.z); l[2] = __float2bfloat16_rn(v.z - __bfloat162float(h[2]));
        h[3] = __float2bfloat16_rn(v.w); l[3] = __float2bfloat16_rn(v.w - __bfloat162float(h[3]));
        *reinterpret_cast<uint2*>(hi + 4 * (size_t)j) = *reinterpret_cast<uint2*>(h);
        *reinterpret_cast<uint2*>(lo + 4 * (size_t)j) = *reinterpret_cast<uint2*>(l);
    }
}

// ---------------------------------------------------------------------------
// Dynamic SMEM layout:
//   [0..16)    s_tkt
//   [16..64)   rsm (reduction scratch)
//   [1024..)   A: 256 rows x 144 B (rows 0-127 = Ahi tokens, 128-255 = Alo)
//   then       B: 2 buffers x 128 rows x 144 B (rows 0-63 = Bhi, 64-127 = Blo)
// ---------------------------------------------------------------------------
#define SM_TKT   0
#define SM_RSM   16
#define SM_A     1024
#define A_BYTES  (256 * STRIDE)          // 36864
#define SM_B0    (SM_A + A_BYTES)        // 37888
#define B_BYTES  (128 * STRIDE)          // 18432
#define SM_TOTAL (SM_B0 + 2 * B_BYTES)   // 74752

// ---------------------------------------------------------------------------
__global__ __launch_bounds__(TPB) void main_kernel(
    const float* __restrict__ tmask,
    const float* __restrict__ imask,
    const int* __restrict__ Iidx,
    const int* __restrict__ Sidx,
    float* __restrict__ out) {
    extern __shared__ char smem[];
    const uint32_t sbase = smem_to_u32(smem);
    float* rsm = (float*)(smem + SM_RSM);
    volatile unsigned* s_tkt = (volatile unsigned*)(smem + SM_TKT);
    const int t = threadIdx.x, w = t >> 5, lane = t & 31;

    for (;;) {
        __syncthreads();                     // protect s_tkt / rsm / smem reuse
        if (t == 0) *s_tkt = atomicAdd(&g_ticket, 1u);
        __syncthreads();
        const unsigned tk = *s_tkt;
        if (tk >= NTICKET) break;

        const int mtile = tk % NMT;
        const int b     = (tk / NMT) % BB;
        const int s     = tk / (BB * NMT);
        const int tb    = (s == 1) ? Sidx[b] : b;   // text batch index
        const int ib    = (s == 2) ? Iidx[b] : b;   // image batch index

        // --- valid counts from prefix masks ---
        float sa = 0.f, sb = 0.f;
        #pragma unroll
        for (int i = 0; i < NN / TPB; i++) sa += tmask[tb * NN + i * TPB + t];
        #pragma unroll
        for (int i = 0; i < LL / TPB; i++) sb += imask[ib * LL + i * TPB + t];
        #pragma unroll
        for (int o = 16; o > 0; o >>= 1) {
            sa += __shfl_down_sync(0xffffffffu, sa, o);
            sb += __shfl_down_sync(0xffffffffu, sb, o);
        }
        if (lane == 0) { rsm[2 * w] = sa; rsm[2 * w + 1] = sb; }
        __syncthreads();
        if (t == 0) {
            rsm[8] = rsm[0] + rsm[2] + rsm[4] + rsm[6];
            rsm[9] = rsm[1] + rsm[3] + rsm[5] + rsm[7];
        }
        __syncthreads();
        const float ntok_f = rsm[8];
        const int ntok = (int)(ntok_f + 0.5f);
        const int nreg = (int)(rsm[9] + 0.5f);
        if (s == 0 && mtile == 0 && t == 0) g_ntokf[b] = ntok_f;

        const int mbase = mtile * MT;
        if (mbase >= ntok) {
            if (t == 0) g_part[tk] = 0.f;
            continue;
        }

        // --- stage A (128 rows hi + 128 rows lo) via cp.async ---
        {
            const char* thi = (const char*)(g_thi + ((size_t)tb * NN + mbase) * DD);
            const char* tlo = (const char*)(g_tlo + ((size_t)tb * NN + mbase) * DD);
            #pragma unroll
            for (int i = 0; i < 2048 / TPB; i++) {    // 256 rows x 8 chunks
                int idx = i * TPB + t;
                int r = idx >> 3, j = idx & 7;
                const char* src = (r < 128) ? thi + r * 128 + j * 16
                                            : tlo + (r - 128) * 128 + j * 16;
                CP_ASYNC16(sbase + SM_A + r * STRIDE + j * 16, src);
            }
        }
        const char* ihi = (const char*)(g_ihi + (size_t)ib * LL * DD);
        const char* ilo = (const char*)(g_ilo + (size_t)ib * LL * DD);
        const int nchunk = (nreg + RB - 1) / RB;

        // stage B chunk 0 (hi rows 0-63, lo rows 64-127)
        {
            int lcount = (nreg < RB) ? nreg : RB;
            for (int i = t; i < lcount * 16; i += TPB) {
                int half = (i >= lcount * 8);
                int ii = i - half * lcount * 8;
                int r = ii >> 3, j = ii & 7;
                const char* src = (half ? ilo : ihi) + r * 128 + j * 16;
                CP_ASYNC16(sbase + SM_B0 + (half * 64 + r) * STRIDE + j * 16, src);
            }
        }
        CP_COMMIT();

        float mx0 = __int_as_float(0xff800000), mx1 = mx0, mx2 = mx0, mx3 = mx0;
        const uint32_t Abase = sbase + SM_A;

        for (int c = 0; c < nchunk; c++) {
            if (c + 1 < nchunk) {                // prefetch next chunk
                int cb2 = (c + 1) * RB;
                int lc2 = nreg - cb2; if (lc2 > RB) lc2 = RB;
                uint32_t dstb = sbase + SM_B0 + ((c + 1) & 1) * B_BYTES;
                for (int i = t; i < lc2 * 16; i += TPB) {
                    int half = (i >= lc2 * 8);
                    int ii = i - half * lc2 * 8;
                    int r = ii >> 3, j = ii & 7;
                    const char* src = (half ? ilo : ihi) + (cb2 + r) * 128 + j * 16;
                    CP_ASYNC16(dstb + (half * 64 + r) * STRIDE + j * 16, src);
                }
            }
            CP_COMMIT();
            CP_WAIT1();                          // chunk c resident
            __syncthreads();

            const uint32_t Bbase = sbase + SM_B0 + (c & 1) * B_BYTES;
            const int cb = c * RB;

            float acc[8][2][4] = {};             // 8 n-tiles x 2 m-tiles x 4

            #pragma unroll
            for (int k = 0; k < 4; k++) {
                const int kb = 32 * k;           // 16 bf16 per k-step
                uint32_t ah0[4], ah1[4], al0[4], al1[4], bh[8][2];
                LDSM4(ah0, a_addr(Abase, 32 * w,      kb, lane));
                LDSM4(ah1, a_addr(Abase, 32 * w + 16, kb, lane));
                #pragma unroll
                for (int nt = 0; nt < 8; nt++)
                    LDSM2(bh[nt], b_addr(Bbase, 8 * nt, kb, lane));
                // term 0: Ahi x Bhi
                #pragma unroll
                for (int nt = 0; nt < 8; nt++) {
                    MMA16816(acc[nt][0], ah0, bh[nt]);
                    MMA16816(acc[nt][1], ah1, bh[nt]);
                }
                // term 1: Ahi x Blo
                #pragma unroll
                for (int nt = 0; nt < 8; nt++) {
                    uint32_t bl[2];
                    LDSM2(bl, b_addr(Bbase, 64 + 8 * nt, kb, lane));
                    MMA16816(acc[nt][0], ah0, bl);
                    MMA16816(acc[nt][1], ah1, bl);
                }
                // term 2: Alo x Bhi
                LDSM4(al0, a_addr(Abase, 128 + 32 * w,      kb, lane));
                LDSM4(al1, a_addr(Abase, 128 + 32 * w + 16, kb, lane));
                #pragma unroll
                for (int nt = 0; nt < 8; nt++) {
                    MMA16816(acc[nt][0], al0, bh[nt]);
                    MMA16816(acc[nt][1], al1, bh[nt]);
                }
            }

            // --- fold accumulators into per-row running maxes ---
            // acc[nt][mt]: d0,d1 -> row lane/4 (+16*mt), cols 2*(lane&3)+{0,1};
            //              d2,d3 -> row +8
            const int nvalid = nreg - cb;
            if (nvalid >= RB) {
                #pragma unroll
                for (int nt = 0; nt < 8; nt++) {
                    mx0 = fmaxf(mx0, fmaxf(acc[nt][0][0], acc[nt][0][1]));
                    mx1 = fmaxf(mx1, fmaxf(acc[nt][0][2], acc[nt][0][3]));
                    mx2 = fmaxf(mx2, fmaxf(acc[nt][1][0], acc[nt][1][1]));
                    mx3 = fmaxf(mx3, fmaxf(acc[nt][1][2], acc[nt][1][3]));
                }
            } else {
                #pragma unroll
                for (int nt = 0; nt < 8; nt++) {
                    const int c0 = cb + 8 * nt + 2 * (lane & 3);
                    if (c0 < nreg) {
                        mx0 = fmaxf(mx0, acc[nt][0][0]);
                        mx1 = fmaxf(mx1, acc[nt][0][2]);
                        mx2 = fmaxf(mx2, acc[nt][1][0]);
                        mx3 = fmaxf(mx3, acc[nt][1][2]);
                    }
                    if (c0 + 1 < nreg) {
                        mx0 = fmaxf(mx0, acc[nt][0][1]);
                        mx1 = fmaxf(mx1, acc[nt][0][3]);
                        mx2 = fmaxf(mx2, acc[nt][1][1]);
                        mx3 = fmaxf(mx3, acc[nt][1][3]);
                    }
                }
            }
            __syncthreads();                     // chunk c free before c+2 load
        }

        // --- quad max-reduce (cols live across the 4 lanes of each quad) ---
        mx0 = fmaxf(mx0, __shfl_xor_sync(0xffffffffu, mx0, 1));
        mx0 = fmaxf(mx0, __shfl_xor_sync(0xffffffffu, mx0, 2));
        mx1 = fmaxf(mx1, __shfl_xor_sync(0xffffffffu, mx1, 1));
        mx1 = fmaxf(mx1, __shfl_xor_sync(0xffffffffu, mx1, 2));
        mx2 = fmaxf(mx2, __shfl_xor_sync(0xffffffffu, mx2, 1));
        mx2 = fmaxf(mx2, __shfl_xor_sync(0xffffffffu, mx2, 2));
        mx3 = fmaxf(mx3, __shfl_xor_sync(0xffffffffu, mx3, 1));
        mx3 = fmaxf(mx3, __shfl_xor_sync(0xffffffffu, mx3, 2));

        // token-sum: rows mbase + 32w + lane/4 + {0,8,16,24}; weight = valid
        float v = 0.f;
        if ((lane & 3) == 0) {
            const int r0 = mbase + 32 * w + (lane >> 2);
            if (r0      < ntok) v += mx0;
            if (r0 + 8  < ntok) v += mx1;
            if (r0 + 16 < ntok) v += mx2;
            if (r0 + 24 < ntok) v += mx3;
        }
        #pragma unroll
        for (int o = 16; o > 0; o >>= 1) v += __shfl_down_sync(0xffffffffu, v, o);
        if (lane == 0) rsm[w] = v;
        __syncthreads();
        if (t == 0) g_part[tk] = rsm[0] + rsm[1] + rsm[2] + rsm[3];
    }

    // ---- completion: last block computes the loss and resets counters ----
    __threadfence();
    __shared__ unsigned int s_prev;
    if (t == 0) s_prev = atomicAdd(&g_done, 1u);
    __syncthreads();
    if (s_prev != GRID - 1) return;
    __threadfence();

    const int bb = t;                            // 128 threads == BB
    float anchor = 0.f, simp = 0.f, iimp = 0.f;
    #pragma unroll
    for (int m = 0; m < NMT; m++) {
        anchor += g_part[(0 * BB + bb) * NMT + m];
        simp   += g_part[(1 * BB + bb) * NMT + m];
        iimp   += g_part[(2 * BB + bb) * NMT + m];
    }
    const float nb = g_ntokf[bb];
    anchor /= nb;
    iimp   /= nb;
    simp   /= g_ntokf[Sidx[bb]];
    float per = fmaxf(1.f + iimp - anchor, 0.f) + fmaxf(1.f + simp - anchor, 0.f);

    #pragma unroll
    for (int o = 16; o > 0; o >>= 1) per += __shfl_down_sync(0xffffffffu, per, o);
    if (lane == 0) rsm[w] = per;
    __syncthreads();
    if (t == 0) {
        out[0] = (rsm[0] + rsm[1] + rsm[2] + rsm[3]) / (float)BB;
        g_ticket = 0u;                           // reset for next replay
        g_done   = 0u;
    }
}

// ---------------------------------------------------------------------------
extern "C" void kernel_launch(void* const* d_in, const int* in_sizes, int n_in,
                              void* d_out, int out_size) {
    const float* text  = (const float*)d_in[0];   // (B, N, D) f32
    const float* image = (const float*)d_in[1];   // (B, L, D) f32
    const float* tmask = (const float*)d_in[2];   // (B, N) f32
    const float* imask = (const float*)d_in[3];   // (B, L) f32
    const int*   Iidx  = (const int*)d_in[4];     // (B,) i32
    const int*   Sidx  = (const int*)d_in[5];     // (B,) i32
    (void)in_sizes; (void)n_in; (void)out_size;

    static int configured = 0;
    if (!configured) {
        cudaFuncSetAttribute(main_kernel,
                             cudaFuncAttributeMaxDynamicSharedMemorySize, SM_TOTAL);
        configured = 1;
    }

    convert_kernel<<<2048, 256>>>(text, image);
    main_kernel<<<GRID, TPB, SM_TOTAL>>>(tmask, imask, Iidx, Sidx, (float*)d_out);
}

// round 13
// speedup vs baseline: 3.2402x; 1.7388x over previous
#include <cuda_runtime.h>
#include <cuda_bf16.h>
#include <cstdint>
#include <cstddef>

// Problem constants
#define BB 128
#define NN 1024
#define LL 512
#define DD 64
#define MT 128                    // tokens per M tile
#define NMT (NN / MT)             // 8 M tiles
#define NTICKET (3 * BB * NMT)    // 3072 work items
#define TPB 128                   // 4 warps; warp owns 32 token rows
#define GRID 296                  // 148 SMs x 2 CTAs
#define RB 64                     // regions per B chunk
#define STRIDE 144                // padded smem row stride bytes -> LDSM conflict-free

// Scratch (no device allocations allowed -> __device__ globals)
__device__ __align__(16) __nv_bfloat16 g_thi[BB * NN * DD];
__device__ __align__(16) __nv_bfloat16 g_tlo[BB * NN * DD];
__device__ __align__(16) __nv_bfloat16 g_ihi[BB * LL * DD];
__device__ __align__(16) __nv_bfloat16 g_ilo[BB * LL * DD];
__device__ float         g_part[NTICKET];
__device__ float         g_ntokf[BB];
__device__ int           g_ntok[BB];
__device__ int           g_nreg[BB];
__device__ unsigned int  g_ticket;   // zero-init; reset by last block
__device__ unsigned int  g_done;

// ---------------------------------------------------------------------------
// PTX helpers (base sm_103 target: sm_80+ features only)
// ---------------------------------------------------------------------------
__device__ __forceinline__ uint32_t smem_to_u32(const void* p) {
    uint32_t a;
    asm("{ .reg .u64 t; cvta.to.shared.u64 t, %1; cvt.u32.u64 %0, t; }"
        : "=r"(a) : "l"(p));
    return a;
}

#define LDSM4(r, addr) \
    asm volatile("ldmatrix.sync.aligned.m8n8.x4.shared.b16 {%0,%1,%2,%3}, [%4];" \
        : "=r"((r)[0]), "=r"((r)[1]), "=r"((r)[2]), "=r"((r)[3]) : "r"(addr))

#define MMA16816(d, a, b) \
    asm volatile("mma.sync.aligned.m16n8k16.row.col.f32.bf16.bf16.f32 " \
        "{%0,%1,%2,%3}, {%4,%5,%6,%7}, {%8,%9}, {%0,%1,%2,%3};" \
        : "+f"((d)[0]), "+f"((d)[1]), "+f"((d)[2]), "+f"((d)[3]) \
        : "r"((a)[0]), "r"((a)[1]), "r"((a)[2]), "r"((a)[3]), \
          "r"((b)[0]), "r"((b)[1]))

#define CP_ASYNC16(dst_s, src_g) \
    asm volatile("cp.async.cg.shared.global [%0], [%1], 16;" :: "r"(dst_s), "l"(src_g))
#define CP_COMMIT() asm volatile("cp.async.commit_group;" ::: "memory")
#define CP_WAIT1()  asm volatile("cp.async.wait_group 1;" ::: "memory")

// ldmatrix x4 address for A tile: 16x16 tile -> mats [r0-7,k0-7][r8-15,k0-7][r0-7,k8-15][r8-15,k8-15]
__device__ __forceinline__ uint32_t a_addr(uint32_t base, int row0, int kb, int lane) {
    int r = row0 + (lane & 7) + ((lane >> 3) & 1) * 8;
    return base + r * STRIDE + kb + ((lane >> 4) & 1) * 16;
}
// ldmatrix x4 address for TWO B n-tiles: mats [n0-7,k0-7][n0-7,k8-15][n8-15,k0-7][n8-15,k8-15]
__device__ __forceinline__ uint32_t b_addr4(uint32_t base, int nrow0, int kb, int lane) {
    int r = nrow0 + ((lane >> 4) & 1) * 8 + (lane & 7);
    return base + r * STRIDE + kb + ((lane >> 3) & 1) * 16;
}

// ---------------------------------------------------------------------------
// convert: fp32 -> (hi, lo) bf16 split; first BB blocks also count mask prefixes
// ---------------------------------------------------------------------------
__global__ void convert_kernel(const float* __restrict__ text,
                               const float* __restrict__ image,
                               const float* __restrict__ tmask,
                               const float* __restrict__ imask) {
    if (blockIdx.x < BB) {
        const int b = blockIdx.x;
        float sa = 0.f, sb = 0.f;
        for (int i = threadIdx.x; i < NN; i += blockDim.x) sa += tmask[b * NN + i];
        for (int i = threadIdx.x; i < LL; i += blockDim.x) sb += imask[b * LL + i];
        __shared__ float red[16];
        #pragma unroll
        for (int o = 16; o > 0; o >>= 1) {
            sa += __shfl_down_sync(0xffffffffu, sa, o);
            sb += __shfl_down_sync(0xffffffffu, sb, o);
        }
        int w = threadIdx.x >> 5, lane = threadIdx.x & 31;
        if (lane == 0) { red[2 * w] = sa; red[2 * w + 1] = sb; }
        __syncthreads();
        if (threadIdx.x == 0) {
            float ta = 0.f, tbv = 0.f;
            #pragma unroll
            for (int i = 0; i < 8; i++) { ta += red[2 * i]; tbv += red[2 * i + 1]; }
            g_ntokf[b] = ta;
            g_ntok[b] = (int)(ta + 0.5f);
            g_nreg[b] = (int)(tbv + 0.5f);
        }
    }

    const int NT4 = (BB * NN * DD) / 4;
    const int NI4 = (BB * LL * DD) / 4;
    int idx = blockIdx.x * blockDim.x + threadIdx.x;
    int stride = gridDim.x * blockDim.x;
    for (int i = idx; i < NT4 + NI4; i += stride) {
        const float4* src; __nv_bfloat16 *hi, *lo; int j;
        if (i < NT4) { src = (const float4*)text;  hi = g_thi; lo = g_tlo; j = i; }
        else         { src = (const float4*)image; hi = g_ihi; lo = g_ilo; j = i - NT4; }
        float4 v = src[j];
        __nv_bfloat16 h[4], l[4];
        h[0] = __float2bfloat16_rn(v.x); l[0] = __float2bfloat16_rn(v.x - __bfloat162float(h[0]));
        h[1] = __float2bfloat16_rn(v.y); l[1] = __float2bfloat16_rn(v.y - __bfloat162float(h[1]));
        h[2] = __float2bfloat16_rn(v.z); l[2] = __float2bfloat16_rn(v.z - __bfloat162float(h[2]));
        h[3] = __float2bfloat16_rn(v.w); l[3] = __float2bfloat16_rn(v.w - __bfloat162float(h[3]));
        *reinterpret_cast<uint2*>(hi + 4 * (size_t)j) = *reinterpret_cast<uint2*>(h);
        *reinterpret_cast<uint2*>(lo + 4 * (size_t)j) = *reinterpret_cast<uint2*>(l);
    }
}

// ---------------------------------------------------------------------------
// Dynamic SMEM layout:
//   [0..16)    s_tkt
//   [16..64)   rsm (reduction scratch)
//   [1024..)   A: 256 rows x 144 B (rows 0-127 = Ahi tokens, 128-255 = Alo)
//   then       B: 2 buffers x 128 rows x 144 B (rows 0-63 = Bhi, 64-127 = Blo)
// ---------------------------------------------------------------------------
#define SM_TKT   0
#define SM_RSM   16
#define SM_A     1024
#define A_BYTES  (256 * STRIDE)          // 36864
#define SM_B0    (SM_A + A_BYTES)        // 37888
#define B_BYTES  (128 * STRIDE)          // 18432
#define SM_TOTAL (SM_B0 + 2 * B_BYTES)   // 74752

// ---------------------------------------------------------------------------
__global__ __launch_bounds__(TPB) void main_kernel(
    const int* __restrict__ Iidx,
    const int* __restrict__ Sidx,
    float* __restrict__ out) {
    extern __shared__ char smem[];
    const uint32_t sbase = smem_to_u32(smem);
    float* rsm = (float*)(smem + SM_RSM);
    volatile unsigned* s_tkt = (volatile unsigned*)(smem + SM_TKT);
    const int t = threadIdx.x, w = t >> 5, lane = t & 31;

    for (;;) {
        __syncthreads();                     // protect s_tkt / rsm / smem reuse
        if (t == 0) *s_tkt = atomicAdd(&g_ticket, 1u);
        __syncthreads();
        const unsigned tk = *s_tkt;
        if (tk >= NTICKET) break;

        const int mtile = tk % NMT;
        const int b     = (tk / NMT) % BB;
        const int s     = tk / (BB * NMT);
        const int tb    = (s == 1) ? Sidx[b] : b;   // text batch index
        const int ib    = (s == 2) ? Iidx[b] : b;   // image batch index
        const int ntok  = g_ntok[tb];
        const int nreg  = g_nreg[ib];

        const int mbase = mtile * MT;
        if (mbase >= ntok) {
            if (t == 0) g_part[tk] = 0.f;
            continue;
        }

        // --- stage A (128 rows hi + 128 rows lo) via cp.async ---
        {
            const char* thi = (const char*)(g_thi + ((size_t)tb * NN + mbase) * DD);
            const char* tlo = (const char*)(g_tlo + ((size_t)tb * NN + mbase) * DD);
            #pragma unroll
            for (int i = 0; i < 2048 / TPB; i++) {    // 256 rows x 8 chunks
                int idx = i * TPB + t;
                int r = idx >> 3, j = idx & 7;
                const char* src = (r < 128) ? thi + r * 128 + j * 16
                                            : tlo + (r - 128) * 128 + j * 16;
                CP_ASYNC16(sbase + SM_A + r * STRIDE + j * 16, src);
            }
        }
        const char* ihi = (const char*)(g_ihi + (size_t)ib * LL * DD);
        const char* ilo = (const char*)(g_ilo + (size_t)ib * LL * DD);
        const int nchunk = (nreg + RB - 1) / RB;      // >= 2 (nreg >= 128)

        // stage B chunk 0 (hi rows 0-63, lo rows 64-127); chunk 0 always full
        {
            #pragma unroll
            for (int i = 0; i < 1024 / TPB; i++) {    // 128 rows x 8 chunks
                int idx = i * TPB + t;
                int r = idx >> 3, j = idx & 7;
                const char* src = (r < 64) ? ihi + r * 128 + j * 16
                                           : ilo + (r - 64) * 128 + j * 16;
                CP_ASYNC16(sbase + SM_B0 + r * STRIDE + j * 16, src);
            }
        }
        CP_COMMIT();

        float mx0 = __int_as_float(0xff800000), mx1 = mx0, mx2 = mx0, mx3 = mx0;
        const uint32_t Abase = sbase + SM_A;

        // A fragments cached in registers across all chunks (loop-invariant)
        uint32_t ah[2][4][4], al[2][4][4];   // [mtile][kstep][frag]

        for (int c = 0; c < nchunk; c++) {
            if (c + 1 < nchunk) {                // prefetch next chunk
                int cb2 = (c + 1) * RB;
                int lc2 = nreg - cb2; if (lc2 > RB) lc2 = RB;
                uint32_t dstb = sbase + SM_B0 + ((c + 1) & 1) * B_BYTES;
                for (int i = t; i < lc2 * 16; i += TPB) {
                    int half = (i >= lc2 * 8);
                    int ii = i - half * lc2 * 8;
                    int r = ii >> 3, j = ii & 7;
                    const char* src = (half ? ilo : ihi) + (cb2 + r) * 128 + j * 16;
                    CP_ASYNC16(dstb + (half * 64 + r) * STRIDE + j * 16, src);
                }
            }
            CP_COMMIT();
            CP_WAIT1();                          // chunk c (and A on c==0) resident
            __syncthreads();

            if (c == 0) {                        // one-time A fragment load
                #pragma unroll
                for (int k = 0; k < 4; k++) {
                    LDSM4(ah[0][k], a_addr(Abase, 32 * w,            32 * k, lane));
                    LDSM4(ah[1][k], a_addr(Abase, 32 * w + 16,       32 * k, lane));
                    LDSM4(al[0][k], a_addr(Abase, 128 + 32 * w,      32 * k, lane));
                    LDSM4(al[1][k], a_addr(Abase, 128 + 32 * w + 16, 32 * k, lane));
                }
            }

            const uint32_t Bbase = sbase + SM_B0 + (c & 1) * B_BYTES;
            const int cb = c * RB;

            float acc[8][2][4] = {};             // 8 n-tiles x 2 m-tiles x 4

            #pragma unroll
            for (int k = 0; k < 4; k++) {
                const int kb = 32 * k;
                uint32_t bh[8][2], bl[8][2];
                #pragma unroll
                for (int np = 0; np < 4; np++) { // x4 loads 2 n-tiles each
                    uint32_t r4[4];
                    LDSM4(r4, b_addr4(Bbase, 16 * np, kb, lane));
                    bh[2 * np][0] = r4[0]; bh[2 * np][1] = r4[1];
                    bh[2 * np + 1][0] = r4[2]; bh[2 * np + 1][1] = r4[3];
                    LDSM4(r4, b_addr4(Bbase, 64 + 16 * np, kb, lane));
                    bl[2 * np][0] = r4[0]; bl[2 * np][1] = r4[1];
                    bl[2 * np + 1][0] = r4[2]; bl[2 * np + 1][1] = r4[3];
                }
                // D = Ahi Bhi + Ahi Blo + Alo Bhi (fp32 accum)
                #pragma unroll
                for (int nt = 0; nt < 8; nt++) {
                    MMA16816(acc[nt][0], ah[0][k], bh[nt]);
                    MMA16816(acc[nt][1], ah[1][k], bh[nt]);
                    MMA16816(acc[nt][0], ah[0][k], bl[nt]);
                    MMA16816(acc[nt][1], ah[1][k], bl[nt]);
                    MMA16816(acc[nt][0], al[0][k], bh[nt]);
                    MMA16816(acc[nt][1], al[1][k], bh[nt]);
                }
            }

            // --- fold accumulators into per-row running maxes ---
            // acc[nt][mt]: d0,d1 -> row lane/4 (+16*mt), cols 2*(lane&3)+{0,1};
            //              d2,d3 -> row +8
            const int nvalid = nreg - cb;
            if (nvalid >= RB) {
                #pragma unroll
                for (int nt = 0; nt < 8; nt++) {
                    mx0 = fmaxf(mx0, fmaxf(acc[nt][0][0], acc[nt][0][1]));
                    mx1 = fmaxf(mx1, fmaxf(acc[nt][0][2], acc[nt][0][3]));
                    mx2 = fmaxf(mx2, fmaxf(acc[nt][1][0], acc[nt][1][1]));
                    mx3 = fmaxf(mx3, fmaxf(acc[nt][1][2], acc[nt][1][3]));
                }
            } else {
                #pragma unroll
                for (int nt = 0; nt < 8; nt++) {
                    const int c0 = cb + 8 * nt + 2 * (lane & 3);
                    if (c0 < nreg) {
                        mx0 = fmaxf(mx0, acc[nt][0][0]);
                        mx1 = fmaxf(mx1, acc[nt][0][2]);
                        mx2 = fmaxf(mx2, acc[nt][1][0]);
                        mx3 = fmaxf(mx3, acc[nt][1][2]);
                    }
                    if (c0 + 1 < nreg) {
                        mx0 = fmaxf(mx0, acc[nt][0][1]);
                        mx1 = fmaxf(mx1, acc[nt][0][3]);
                        mx2 = fmaxf(mx2, acc[nt][1][1]);
                        mx3 = fmaxf(mx3, acc[nt][1][3]);
                    }
                }
            }
            __syncthreads();                     // chunk c free before c+2 load
        }

        // --- quad max-reduce (cols live across the 4 lanes of each quad) ---
        mx0 = fmaxf(mx0, __shfl_xor_sync(0xffffffffu, mx0, 1));
        mx0 = fmaxf(mx0, __shfl_xor_sync(0xffffffffu, mx0, 2));
        mx1 = fmaxf(mx1, __shfl_xor_sync(0xffffffffu, mx1, 1));
        mx1 = fmaxf(mx1, __shfl_xor_sync(0xffffffffu, mx1, 2));
        mx2 = fmaxf(mx2, __shfl_xor_sync(0xffffffffu, mx2, 1));
        mx2 = fmaxf(mx2, __shfl_xor_sync(0xffffffffu, mx2, 2));
        mx3 = fmaxf(mx3, __shfl_xor_sync(0xffffffffu, mx3, 1));
        mx3 = fmaxf(mx3, __shfl_xor_sync(0xffffffffu, mx3, 2));

        // token-sum: rows mbase + 32w + lane/4 + {0,8,16,24}; weight = valid
        float v = 0.f;
        if ((lane & 3) == 0) {
            const int r0 = mbase + 32 * w + (lane >> 2);
            if (r0      < ntok) v += mx0;
            if (r0 + 8  < ntok) v += mx1;
            if (r0 + 16 < ntok) v += mx2;
            if (r0 + 24 < ntok) v += mx3;
        }
        #pragma unroll
        for (int o = 16; o > 0; o >>= 1) v += __shfl_down_sync(0xffffffffu, v, o);
        if (lane == 0) rsm[w] = v;
        __syncthreads();
        if (t == 0) g_part[tk] = rsm[0] + rsm[1] + rsm[2] + rsm[3];
    }

    // ---- completion: last block computes the loss and resets counters ----
    __threadfence();
    __shared__ unsigned int s_prev;
    if (t == 0) s_prev = atomicAdd(&g_done, 1u);
    __syncthreads();
    if (s_prev != GRID - 1) return;
    __threadfence();

    const int bb = t;                            // 128 threads == BB
    float anchor = 0.f, simp = 0.f, iimp = 0.f;
    #pragma unroll
    for (int m = 0; m < NMT; m++) {
        anchor += g_part[(0 * BB + bb) * NMT + m];
        simp   += g_part[(1 * BB + bb) * NMT + m];
        iimp   += g_part[(2 * BB + bb) * NMT + m];
    }
    const float nb = g_ntokf[bb];
    anchor /= nb;
    iimp   /= nb;
    simp   /= g_ntokf[Sidx[bb]];
    float per = fmaxf(1.f + iimp - anchor, 0.f) + fmaxf(1.f + simp - anchor, 0.f);

    #pragma unroll
    for (int o = 16; o > 0; o >>= 1) per += __shfl_down_sync(0xffffffffu, per, o);
    if (lane == 0) rsm[w] = per;
    __syncthreads();
    if (t == 0) {
        out[0] = (rsm[0] + rsm[1] + rsm[2] + rsm[3]) / (float)BB;
        g_ticket = 0u;                           // reset for next replay
        g_done   = 0u;
    }
}

// ---------------------------------------------------------------------------
extern "C" void kernel_launch(void* const* d_in, const int* in_sizes, int n_in,
                              void* d_out, int out_size) {
    const float* text  = (const float*)d_in[0];   // (B, N, D) f32
    const float* image = (const float*)d_in[1];   // (B, L, D) f32
    const float* tmask = (const float*)d_in[2];   // (B, N) f32
    const float* imask = (const float*)d_in[3];   // (B, L) f32
    const int*   Iidx  = (const int*)d_in[4];     // (B,) i32
    const int*   Sidx  = (const int*)d_in[5];     // (B,) i32
    (void)in_sizes; (void)n_in; (void)out_size;

    static int configured = 0;
    if (!configured) {
        cudaFuncSetAttribute(main_kernel,
                             cudaFuncAttributeMaxDynamicSharedMemorySize, SM_TOTAL);
        configured = 1;
    }

    convert_kernel<<<2048, 256>>>(text, image, tmask, imask);
    main_kernel<<<GRID, TPB, SM_TOTAL>>>(Iidx, Sidx, (float*)d_out);
}